// round 4
// baseline (speedup 1.0000x reference)
#include <cuda_runtime.h>
#include <cstdint>

#define N_NODES 50000
#define N_EDGES 800000
#define IN_DIM  64
#define HID_DIM 64
#define OUT_DIM 32

// Scratch: __device__ globals (allocation is forbidden)
__device__ __align__(16) float g_aggr1[N_NODES * IN_DIM];
__device__ __align__(16) float g_h[N_NODES * HID_DIM];
__device__ __align__(16) float g_aggr2[N_NODES * HID_DIM];
__device__ __align__(16) float g_cnt[N_NODES];

// ---------------------------------------------------------------------------
// Edge aggregation: thread = (edge, float4 chunk). red.global.add.v4.f32
// no-return reductions (4x fewer atomic ops than scalar).
// edge_index is int32 on device (JAX silently downcasts int64).
// ---------------------------------------------------------------------------
__global__ void edge_aggregate_kernel(const float* __restrict__ feat,
                                      const int* __restrict__ ei,
                                      float* __restrict__ aggr,
                                      float* __restrict__ cnt,
                                      int do_count)
{
    int idx = blockIdx.x * blockDim.x + threadIdx.x;
    const int total = N_EDGES * 16;
    if (idx >= total) return;
    int e = idx >> 4;
    int c = idx & 15;

    int src = ei[e];
    int dst = ei[N_EDGES + e];

    const float4* srow = reinterpret_cast<const float4*>(feat + (size_t)src * 64);
    float4 v = srow[c];

    float* p = aggr + (size_t)dst * 64 + c * 4;
    asm volatile("red.global.add.v4.f32 [%0], {%1, %2, %3, %4};"
                 :: "l"(p), "f"(v.x), "f"(v.y), "f"(v.z), "f"(v.w)
                 : "memory");

    if (do_count && c == 0) {
        atomicAdd(cnt + dst, 1.0f);
    }
}

// ---------------------------------------------------------------------------
// Node update: out[n] = act( (aggr[n]/max(cnt,1)) @ Wl^T + bl + x[n] @ Wr^T )
//
// Each thread computes 8 outputs for one node. Per k-step per thread:
//   2 scalar broadcasts (sa, sx) + 4 LDS.128 (weight float4s) -> 16 FMAs.
// STATIC shared memory, exactly 48KB per block (no cudaFuncSetAttribute, no
// dynamic smem, graph-capture clean). Feature rows unpadded (stride 64);
// the resulting 4/8-way broadcast conflicts are absorbed by the FFMA bound.
// ---------------------------------------------------------------------------
template <int OUT, bool RELU>
__global__ void __launch_bounds__(256)
node_update_kernel(const float* __restrict__ x,
                   const float* __restrict__ aggr,
                   const float* __restrict__ cnt,
                   const float* __restrict__ Wl,
                   const float* __restrict__ bl,
                   const float* __restrict__ Wr,
                   float* __restrict__ out)
{
    constexpr int IN  = 64;
    constexpr int OPT = 8;            // outputs per thread
    constexpr int TPN = OUT / OPT;    // threads per node (8 or 4)
    constexpr int NPB = 256 / TPN;    // nodes per tile   (32 or 64)

    __shared__ float sWl[IN * OUT];       // transposed: [k*OUT + t]
    __shared__ float sWr[IN * OUT];
    __shared__ float sx[NPB * IN];
    __shared__ float sa[NPB * IN];
    // total bytes: OUT=64 -> 32768+16384 = 49152; OUT=32 -> 16384+32768 = 49152

    const int tid = threadIdx.x;

    // Stage weights transposed: sW[k*OUT + t] = W[t*IN + k].
    for (int i = tid; i < IN * OUT; i += 256) {
        int t = i % OUT;
        int k = i / OUT;
        sWl[i] = __ldg(&Wl[t * IN + k]);
        sWr[i] = __ldg(&Wr[t * IN + k]);
    }

    const int node_in_blk = tid / TPN;
    const int tq          = tid % TPN;    // which 8-output slice

    // Bias into registers (constant per thread across all tiles)
    float4 b0 = __ldg((const float4*)(bl + tq * 8));
    float4 b1 = __ldg((const float4*)(bl + tq * 8 + 4));

    for (int base = blockIdx.x * NPB; base < N_NODES; base += gridDim.x * NPB) {
        __syncthreads();  // weights ready (1st iter) / sx,sa reuse safe
        // Stage features + normalized aggregates (float4 in, float4 to SMEM)
        for (int i = tid; i < NPB * (IN / 4); i += 256) {
            int nl = i / (IN / 4);
            int kq = i % (IN / 4);
            int n  = base + nl;
            if (n < N_NODES) {
                float inv = 1.0f / fmaxf(cnt[n], 1.0f);
                float4 xv = __ldg((const float4*)(x    + (size_t)n * IN + kq * 4));
                float4 av = __ldg((const float4*)(aggr + (size_t)n * IN + kq * 4));
                av.x *= inv; av.y *= inv; av.z *= inv; av.w *= inv;
                ((float4*)(sx + nl * IN))[kq] = xv;
                ((float4*)(sa + nl * IN))[kq] = av;
            }
        }
        __syncthreads();

        int n = base + node_in_blk;
        if (n < N_NODES) {
            float4 acc0 = b0, acc1 = b1;
            const float* frow_a = sa + node_in_blk * IN;
            const float* frow_x = sx + node_in_blk * IN;
#pragma unroll 8
            for (int k = 0; k < IN; k++) {
                float a  = frow_a[k];
                float xv = frow_x[k];
                const float4* wl = (const float4*)(sWl + k * OUT + tq * 8);
                const float4* wr = (const float4*)(sWr + k * OUT + tq * 8);
                float4 l0 = wl[0], l1 = wl[1];
                float4 r0 = wr[0], r1 = wr[1];
                acc0.x += a * l0.x + xv * r0.x;
                acc0.y += a * l0.y + xv * r0.y;
                acc0.z += a * l0.z + xv * r0.z;
                acc0.w += a * l0.w + xv * r0.w;
                acc1.x += a * l1.x + xv * r1.x;
                acc1.y += a * l1.y + xv * r1.y;
                acc1.z += a * l1.z + xv * r1.z;
                acc1.w += a * l1.w + xv * r1.w;
            }
            if (RELU) {
                acc0.x = fmaxf(acc0.x, 0.0f); acc0.y = fmaxf(acc0.y, 0.0f);
                acc0.z = fmaxf(acc0.z, 0.0f); acc0.w = fmaxf(acc0.w, 0.0f);
                acc1.x = fmaxf(acc1.x, 0.0f); acc1.y = fmaxf(acc1.y, 0.0f);
                acc1.z = fmaxf(acc1.z, 0.0f); acc1.w = fmaxf(acc1.w, 0.0f);
            }
            float4* po = (float4*)(out + (size_t)n * OUT + tq * 8);
            po[0] = acc0;
            po[1] = acc1;
        }
    }
}

// ---------------------------------------------------------------------------
// Launch (no statics, no attribute calls — fully capture-clean)
// ---------------------------------------------------------------------------
extern "C" void kernel_launch(void* const* d_in, const int* in_sizes, int n_in,
                              void* d_out, int out_size)
{
    const float* x   = (const float*)d_in[0];
    const int*   ei  = (const int*)d_in[1];
    const float* Wl1 = (const float*)d_in[2];
    const float* bl1 = (const float*)d_in[3];
    const float* Wr1 = (const float*)d_in[4];
    const float* Wl2 = (const float*)d_in[5];
    const float* bl2 = (const float*)d_in[6];
    const float* Wr2 = (const float*)d_in[7];
    float*       out = (float*)d_out;

    float *aggr1, *h, *aggr2, *cnt;
    cudaGetSymbolAddress((void**)&aggr1, g_aggr1);
    cudaGetSymbolAddress((void**)&h,     g_h);
    cudaGetSymbolAddress((void**)&aggr2, g_aggr2);
    cudaGetSymbolAddress((void**)&cnt,   g_cnt);

    cudaMemsetAsync(aggr1, 0, sizeof(float) * N_NODES * IN_DIM,  0);
    cudaMemsetAsync(aggr2, 0, sizeof(float) * N_NODES * HID_DIM, 0);
    cudaMemsetAsync(cnt,   0, sizeof(float) * N_NODES,           0);

    const int edge_threads = N_EDGES * 16;
    const int edge_blocks  = (edge_threads + 255) / 256;

    // Layer 1
    edge_aggregate_kernel<<<edge_blocks, 256>>>(x, ei, aggr1, cnt, 1);
    node_update_kernel<HID_DIM, true><<<592, 256>>>(x, aggr1, cnt,
                                                    Wl1, bl1, Wr1, h);
    // Layer 2
    edge_aggregate_kernel<<<edge_blocks, 256>>>(h, ei, aggr2, cnt, 0);
    node_update_kernel<OUT_DIM, false><<<592, 256>>>(h, aggr2, cnt,
                                                     Wl2, bl2, Wr2, out);
}

// round 6
// speedup vs baseline: 1.0153x; 1.0153x over previous
#include <cuda_runtime.h>
#include <cstdint>

#define N_NODES 50000
#define N_EDGES 800000
#define IN_DIM  64
#define HID_DIM 64
#define OUT_DIM 32

// Scratch: __device__ globals (allocation is forbidden)
__device__ __align__(16) float g_aggr1[N_NODES * IN_DIM];
__device__ __align__(16) float g_h[N_NODES * HID_DIM];
__device__ __align__(16) float g_aggr2[N_NODES * HID_DIM];
__device__ __align__(16) float g_cnt[N_NODES];

// ---------------------------------------------------------------------------
// Edge aggregation: thread = (edge, float4 chunk). red.global.add.v4.f32
// no-return reductions (4x fewer atomic ops than scalar).
// edge_index is int32 on device (JAX silently downcasts int64).
// ---------------------------------------------------------------------------
__global__ void edge_aggregate_kernel(const float* __restrict__ feat,
                                      const int* __restrict__ ei,
                                      float* __restrict__ aggr,
                                      float* __restrict__ cnt,
                                      int do_count)
{
    int idx = blockIdx.x * blockDim.x + threadIdx.x;
    const int total = N_EDGES * 16;
    if (idx >= total) return;
    int e = idx >> 4;
    int c = idx & 15;

    int src = ei[e];
    int dst = ei[N_EDGES + e];

    const float4* srow = reinterpret_cast<const float4*>(feat + (size_t)src * 64);
    float4 v = srow[c];

    float* p = aggr + (size_t)dst * 64 + c * 4;
    asm volatile("red.global.add.v4.f32 [%0], {%1, %2, %3, %4};"
                 :: "l"(p), "f"(v.x), "f"(v.y), "f"(v.z), "f"(v.w)
                 : "memory");

    if (do_count && c == 0) {
        atomicAdd(cnt + dst, 1.0f);
    }
}

// ---------------------------------------------------------------------------
// Node update: out[n] = act( (aggr[n]/max(cnt,1)) @ Wl^T + bl + x[n] @ Wr^T )
//
// Thread computes 8 outputs for one node. Feature rows are stored XOR-
// SWIZZLED in SMEM: float4 chunk kq of node nl lives at slot (kq ^ (nl&7)).
// For a fixed k, the 8 (resp. 4) distinct nodes in a warp then read from
// distinct banks -> the previous 8-way broadcast conflict (L1=76% bound in
// R4's profile) disappears. Weight LDS.128s are broadcast reads (4/8 unique
// 16B addrs per warp) and already conflict-free.
// Static SMEM, exactly 48KB -> graph-capture clean.
// ---------------------------------------------------------------------------
template <int OUT, bool RELU>
__global__ void __launch_bounds__(256)
node_update_kernel(const float* __restrict__ x,
                   const float* __restrict__ aggr,
                   const float* __restrict__ cnt,
                   const float* __restrict__ Wl,
                   const float* __restrict__ bl,
                   const float* __restrict__ Wr,
                   float* __restrict__ out)
{
    constexpr int IN  = 64;
    constexpr int OPT = 8;            // outputs per thread
    constexpr int TPN = OUT / OPT;    // threads per node (8 or 4)
    constexpr int NPB = 256 / TPN;    // nodes per tile   (32 or 64)

    __shared__ float sWl[IN * OUT];       // transposed: [k*OUT + t]
    __shared__ float sWr[IN * OUT];
    __shared__ float sx[NPB * IN];        // swizzled rows
    __shared__ float sa[NPB * IN];        // swizzled rows
    // total bytes: OUT=64 -> 32768+16384 = 49152; OUT=32 -> 16384+32768 = 49152

    const int tid = threadIdx.x;

    // Stage weights transposed: sW[k*OUT + t] = W[t*IN + k].
    for (int i = tid; i < IN * OUT; i += 256) {
        int t = i % OUT;
        int k = i / OUT;
        sWl[i] = __ldg(&Wl[t * IN + k]);
        sWr[i] = __ldg(&Wr[t * IN + k]);
    }

    const int node_in_blk = tid / TPN;
    const int tq          = tid % TPN;      // which 8-output slice
    const int swz         = node_in_blk & 7;  // float4-slot XOR key

    // Bias into registers (constant per thread across all tiles)
    float4 b0 = __ldg((const float4*)(bl + tq * 8));
    float4 b1 = __ldg((const float4*)(bl + tq * 8 + 4));

    for (int base = blockIdx.x * NPB; base < N_NODES; base += gridDim.x * NPB) {
        __syncthreads();  // weights ready (1st iter) / sx,sa reuse safe
        // Stage features + normalized aggregates, swizzled float4 stores
        for (int i = tid; i < NPB * (IN / 4); i += 256) {
            int nl = i / (IN / 4);
            int kq = i % (IN / 4);
            int n  = base + nl;
            if (n < N_NODES) {
                float inv = 1.0f / fmaxf(cnt[n], 1.0f);
                float4 xv = __ldg((const float4*)(x    + (size_t)n * IN + kq * 4));
                float4 av = __ldg((const float4*)(aggr + (size_t)n * IN + kq * 4));
                av.x *= inv; av.y *= inv; av.z *= inv; av.w *= inv;
                int slot = kq ^ (nl & 7);
                ((float4*)(sx + nl * IN))[slot] = xv;
                ((float4*)(sa + nl * IN))[slot] = av;
            }
        }
        __syncthreads();

        int n = base + node_in_blk;
        if (n < N_NODES) {
            float4 acc0 = b0, acc1 = b1;
            const float* frow_a = sa + node_in_blk * IN;
            const float* frow_x = sx + node_in_blk * IN;
#pragma unroll 8
            for (int k = 0; k < IN; k++) {
                int ks   = k ^ (swz << 2);        // swizzled scalar index
                float a  = frow_a[ks];
                float xv = frow_x[ks];
                const float4* wl = (const float4*)(sWl + k * OUT + tq * 8);
                const float4* wr = (const float4*)(sWr + k * OUT + tq * 8);
                float4 l0 = wl[0], l1 = wl[1];
                float4 r0 = wr[0], r1 = wr[1];
                acc0.x += a * l0.x + xv * r0.x;
                acc0.y += a * l0.y + xv * r0.y;
                acc0.z += a * l0.z + xv * r0.z;
                acc0.w += a * l0.w + xv * r0.w;
                acc1.x += a * l1.x + xv * r1.x;
                acc1.y += a * l1.y + xv * r1.y;
                acc1.z += a * l1.z + xv * r1.z;
                acc1.w += a * l1.w + xv * r1.w;
            }
            if (RELU) {
                acc0.x = fmaxf(acc0.x, 0.0f); acc0.y = fmaxf(acc0.y, 0.0f);
                acc0.z = fmaxf(acc0.z, 0.0f); acc0.w = fmaxf(acc0.w, 0.0f);
                acc1.x = fmaxf(acc1.x, 0.0f); acc1.y = fmaxf(acc1.y, 0.0f);
                acc1.z = fmaxf(acc1.z, 0.0f); acc1.w = fmaxf(acc1.w, 0.0f);
            }
            float4* po = (float4*)(out + (size_t)n * OUT + tq * 8);
            po[0] = acc0;
            po[1] = acc1;
        }
    }
}

// ---------------------------------------------------------------------------
// Launch (no statics, no attribute calls — fully capture-clean)
// ---------------------------------------------------------------------------
extern "C" void kernel_launch(void* const* d_in, const int* in_sizes, int n_in,
                              void* d_out, int out_size)
{
    const float* x   = (const float*)d_in[0];
    const int*   ei  = (const int*)d_in[1];
    const float* Wl1 = (const float*)d_in[2];
    const float* bl1 = (const float*)d_in[3];
    const float* Wr1 = (const float*)d_in[4];
    const float* Wl2 = (const float*)d_in[5];
    const float* bl2 = (const float*)d_in[6];
    const float* Wr2 = (const float*)d_in[7];
    float*       out = (float*)d_out;

    float *aggr1, *h, *aggr2, *cnt;
    cudaGetSymbolAddress((void**)&aggr1, g_aggr1);
    cudaGetSymbolAddress((void**)&h,     g_h);
    cudaGetSymbolAddress((void**)&aggr2, g_aggr2);
    cudaGetSymbolAddress((void**)&cnt,   g_cnt);

    cudaMemsetAsync(aggr1, 0, sizeof(float) * N_NODES * IN_DIM,  0);
    cudaMemsetAsync(aggr2, 0, sizeof(float) * N_NODES * HID_DIM, 0);
    cudaMemsetAsync(cnt,   0, sizeof(float) * N_NODES,           0);

    const int edge_threads = N_EDGES * 16;
    const int edge_blocks  = (edge_threads + 255) / 256;

    // Layer 1
    edge_aggregate_kernel<<<edge_blocks, 256>>>(x, ei, aggr1, cnt, 1);
    node_update_kernel<HID_DIM, true><<<592, 256>>>(x, aggr1, cnt,
                                                    Wl1, bl1, Wr1, h);
    // Layer 2
    edge_aggregate_kernel<<<edge_blocks, 256>>>(h, ei, aggr2, cnt, 0);
    node_update_kernel<OUT_DIM, false><<<592, 256>>>(h, aggr2, cnt,
                                                     Wl2, bl2, Wr2, out);
}

// round 8
// speedup vs baseline: 1.3619x; 1.3413x over previous
#include <cuda_runtime.h>
#include <cstdint>

#define N_NODES 50000
#define N_EDGES 800000
#define IN_DIM  64
#define HID_DIM 64
#define OUT_DIM 32

// Scratch: __device__ globals (allocation is forbidden)
__device__ __align__(16) float g_aggr1[N_NODES * IN_DIM];
__device__ __align__(16) float g_h[N_NODES * HID_DIM];
__device__ __align__(16) float g_aggr2[N_NODES * HID_DIM];
__device__ __align__(16) float g_cnt[N_NODES];

// ---------------------------------------------------------------------------
// Edge aggregation (unchanged): thread = (edge, float4 chunk),
// red.global.add.v4.f32 no-return reductions.
// ---------------------------------------------------------------------------
__global__ void edge_aggregate_kernel(const float* __restrict__ feat,
                                      const int* __restrict__ ei,
                                      float* __restrict__ aggr,
                                      float* __restrict__ cnt,
                                      int do_count)
{
    int idx = blockIdx.x * blockDim.x + threadIdx.x;
    const int total = N_EDGES * 16;
    if (idx >= total) return;
    int e = idx >> 4;
    int c = idx & 15;

    int src = ei[e];
    int dst = ei[N_EDGES + e];

    const float4* srow = reinterpret_cast<const float4*>(feat + (size_t)src * 64);
    float4 v = srow[c];

    float* p = aggr + (size_t)dst * 64 + c * 4;
    asm volatile("red.global.add.v4.f32 [%0], {%1, %2, %3, %4};"
                 :: "l"(p), "f"(v.x), "f"(v.y), "f"(v.z), "f"(v.w)
                 : "memory");

    if (do_count && c == 0) {
        atomicAdd(cnt + dst, 1.0f);
    }
}

// Component permute: out[i] = in[i ^ p], p in {0,1,2,3}
__device__ __forceinline__ float4 perm4(float4 v, int p)
{
    if (p & 1) { float t = v.x; v.x = v.y; v.y = t; t = v.z; v.z = v.w; v.w = t; }
    if (p & 2) { float t = v.x; v.x = v.z; v.z = t; t = v.y; v.y = v.w; v.w = t; }
    return v;
}

// ---------------------------------------------------------------------------
// Node update v3: warp-uniform weights + fully bank-spread features.
//
//  - warp = 32 nodes (lane == node) x one 16-output slice
//  - weight LDS.128s: identical address across the warp -> broadcast (1 wf)
//  - feature scalar k of node nl stored at nl*64 + (k ^ (nl&31)):
//    for fixed k the 32 lanes read 32 distinct banks -> conflict-free
//  - per thread-k: 32 FMAs / 10 LDS (8 broadcast) -> FFMA-pipe bound
//  - block = 128 threads; static SMEM exactly 48KB for both instantiations
// ---------------------------------------------------------------------------
template <int OUT, bool RELU>
__global__ void __launch_bounds__(128)
node_update_kernel(const float* __restrict__ x,
                   const float* __restrict__ aggr,
                   const float* __restrict__ cnt,
                   const float* __restrict__ Wl,
                   const float* __restrict__ bl,
                   const float* __restrict__ Wr,
                   float* __restrict__ out)
{
    constexpr int IN     = 64;
    constexpr int SLICES = OUT / 16;      // 4 (OUT=64) or 2 (OUT=32)
    constexpr int GROUPS = 4 / SLICES;    // node-groups per block: 1 or 2
    constexpr int NPB    = 32 * GROUPS;   // nodes per tile: 32 or 64

    __shared__ float sWl[IN * OUT];       // transposed: [k*OUT + t]
    __shared__ float sWr[IN * OUT];
    __shared__ float sa[NPB * IN];        // swizzled feature rows
    __shared__ float sx[NPB * IN];
    // bytes: OUT=64 -> 16K+16K+8K+8K = 48K; OUT=32 -> 8K+8K+16K+16K = 48K

    const int tid   = threadIdx.x;
    const int wid   = tid >> 5;
    const int lane  = tid & 31;
    const int slice = wid % SLICES;
    const int group = wid / SLICES;
    const int nloc  = group * 32 + lane;  // local node index; key = nloc&31 = lane

    // Stage weights transposed: sW[k*OUT + t] = W[t*IN + k]
    for (int i = tid; i < IN * OUT; i += 128) {
        int t = i % OUT;
        int k = i / OUT;
        sWl[i] = __ldg(&Wl[t * IN + k]);
        sWr[i] = __ldg(&Wr[t * IN + k]);
    }

    // Bias (same for whole warp)
    const float4* blv = (const float4*)(bl + slice * 16);
    float4 b0 = __ldg(blv + 0), b1 = __ldg(blv + 1),
           b2 = __ldg(blv + 2), b3 = __ldg(blv + 3);

    for (int base = blockIdx.x * NPB; base < N_NODES; base += gridDim.x * NPB) {
        __syncthreads();
        // Stage features + normalized aggregates, scalar-XOR swizzled.
        // scalar k of node nl -> index nl*64 + (k ^ (nl&31));
        // as float4: quad slot kq ^ (m>>2), components permuted by m&3.
        for (int i = tid; i < NPB * (IN / 4); i += 128) {
            int nl = i / (IN / 4);
            int kq = i % (IN / 4);
            int n  = base + nl;
            if (n < N_NODES) {
                float inv = 1.0f / fmaxf(cnt[n], 1.0f);
                float4 xv = __ldg((const float4*)(x    + (size_t)n * IN + kq * 4));
                float4 av = __ldg((const float4*)(aggr + (size_t)n * IN + kq * 4));
                av.x *= inv; av.y *= inv; av.z *= inv; av.w *= inv;
                int m    = nl & 31;
                int slot = kq ^ (m >> 2);
                int p    = m & 3;
                ((float4*)(sx + nl * IN))[slot] = perm4(xv, p);
                ((float4*)(sa + nl * IN))[slot] = perm4(av, p);
            }
        }
        __syncthreads();

        int n = base + nloc;
        if (n < N_NODES) {
            float4 a0 = b0, a1 = b1, a2 = b2, a3 = b3;
            const float* pa = sa + nloc * IN;
            const float* px = sx + nloc * IN;
#pragma unroll 4
            for (int k = 0; k < IN; k++) {
                int ks   = k ^ lane;              // stays in [0,64)
                float av = pa[ks];
                float xv = px[ks];
                const float4* wl = (const float4*)(sWl + k * OUT + slice * 16);
                const float4* wr = (const float4*)(sWr + k * OUT + slice * 16);
                float4 l0 = wl[0], l1 = wl[1], l2 = wl[2], l3 = wl[3];
                float4 r0 = wr[0], r1 = wr[1], r2 = wr[2], r3 = wr[3];
                a0.x += av * l0.x + xv * r0.x;  a0.y += av * l0.y + xv * r0.y;
                a0.z += av * l0.z + xv * r0.z;  a0.w += av * l0.w + xv * r0.w;
                a1.x += av * l1.x + xv * r1.x;  a1.y += av * l1.y + xv * r1.y;
                a1.z += av * l1.z + xv * r1.z;  a1.w += av * l1.w + xv * r1.w;
                a2.x += av * l2.x + xv * r2.x;  a2.y += av * l2.y + xv * r2.y;
                a2.z += av * l2.z + xv * r2.z;  a2.w += av * l2.w + xv * r2.w;
                a3.x += av * l3.x + xv * r3.x;  a3.y += av * l3.y + xv * r3.y;
                a3.z += av * l3.z + xv * r3.z;  a3.w += av * l3.w + xv * r3.w;
            }
            if (RELU) {
                a0.x = fmaxf(a0.x, 0.f); a0.y = fmaxf(a0.y, 0.f);
                a0.z = fmaxf(a0.z, 0.f); a0.w = fmaxf(a0.w, 0.f);
                a1.x = fmaxf(a1.x, 0.f); a1.y = fmaxf(a1.y, 0.f);
                a1.z = fmaxf(a1.z, 0.f); a1.w = fmaxf(a1.w, 0.f);
                a2.x = fmaxf(a2.x, 0.f); a2.y = fmaxf(a2.y, 0.f);
                a2.z = fmaxf(a2.z, 0.f); a2.w = fmaxf(a2.w, 0.f);
                a3.x = fmaxf(a3.x, 0.f); a3.y = fmaxf(a3.y, 0.f);
                a3.z = fmaxf(a3.z, 0.f); a3.w = fmaxf(a3.w, 0.f);
            }
            float4* po = (float4*)(out + (size_t)n * OUT + slice * 16);
            po[0] = a0; po[1] = a1; po[2] = a2; po[3] = a3;
        }
    }
}

// ---------------------------------------------------------------------------
// Launch (no statics, no attribute calls — fully capture-clean)
// ---------------------------------------------------------------------------
extern "C" void kernel_launch(void* const* d_in, const int* in_sizes, int n_in,
                              void* d_out, int out_size)
{
    const float* x   = (const float*)d_in[0];
    const int*   ei  = (const int*)d_in[1];
    const float* Wl1 = (const float*)d_in[2];
    const float* bl1 = (const float*)d_in[3];
    const float* Wr1 = (const float*)d_in[4];
    const float* Wl2 = (const float*)d_in[5];
    const float* bl2 = (const float*)d_in[6];
    const float* Wr2 = (const float*)d_in[7];
    float*       out = (float*)d_out;

    float *aggr1, *h, *aggr2, *cnt;
    cudaGetSymbolAddress((void**)&aggr1, g_aggr1);
    cudaGetSymbolAddress((void**)&h,     g_h);
    cudaGetSymbolAddress((void**)&aggr2, g_aggr2);
    cudaGetSymbolAddress((void**)&cnt,   g_cnt);

    cudaMemsetAsync(aggr1, 0, sizeof(float) * N_NODES * IN_DIM,  0);
    cudaMemsetAsync(aggr2, 0, sizeof(float) * N_NODES * HID_DIM, 0);
    cudaMemsetAsync(cnt,   0, sizeof(float) * N_NODES,           0);

    const int edge_threads = N_EDGES * 16;
    const int edge_blocks  = (edge_threads + 255) / 256;

    // Layer 1
    edge_aggregate_kernel<<<edge_blocks, 256>>>(x, ei, aggr1, cnt, 1);
    node_update_kernel<HID_DIM, true><<<592, 128>>>(x, aggr1, cnt,
                                                    Wl1, bl1, Wr1, h);
    // Layer 2
    edge_aggregate_kernel<<<edge_blocks, 256>>>(h, ei, aggr2, cnt, 0);
    node_update_kernel<OUT_DIM, false><<<592, 128>>>(h, aggr2, cnt,
                                                     Wl2, bl2, Wr2, out);
}